// round 5
// baseline (speedup 1.0000x reference)
#include <cuda_runtime.h>
#include <cuda_fp16.h>
#include <cstdint>

// B=4, S=2048, D=1024, H=16, depth=64
static constexpr int BBc = 4;
static constexpr int SSc = 2048;
static constexpr int HHc = 16;
static constexpr size_t OUT_ELEMS  = (size_t)8388608;    // B*S*D
static constexpr size_t ATTN_ELEMS = (size_t)268435456;  // B*H*S*S

// Static scratch
__device__ __half g_qh[OUT_ELEMS];        // [B*H][2048][64] fp16
__device__ __half g_kh[OUT_ELEMS];        // [B*H][2048][64] fp16
__device__ __half g_vTh[OUT_ELEMS];       // [B*H][64][2048] fp16
__device__ float  g_rep[OUT_ELEMS];       // [B,S,D] concat fp32
__device__ float  g_wt[4][1024 * 1024];   // transposed weights [n][k]
__device__ float  g_attn_fb[ATTN_ELEMS];  // fallback

__device__ __forceinline__ uint32_t smem_u32(const void* p) {
    uint32_t a;
    asm("{ .reg .u64 t; cvta.to.shared.u64 t, %1; cvt.u32.u64 %0, t; }" : "=r"(a) : "l"(p));
    return a;
}
__device__ __forceinline__ uint32_t f2tf32(float f) {
    uint32_t r;
    asm("cvt.rna.tf32.f32 %0, %1;" : "=r"(r) : "f"(f));
    return r;
}
__device__ __forceinline__ uint32_t pack_h2(float lo, float hi) {
    uint32_t r;
    asm("cvt.rn.f16x2.f32 %0, %1, %2;" : "=r"(r) : "f"(hi), "f"(lo));
    return r;
}
__device__ __forceinline__ void mma_f16(float* c, const uint32_t* a, uint32_t b0, uint32_t b1) {
    asm volatile(
        "mma.sync.aligned.m16n8k16.row.col.f32.f16.f16.f32 "
        "{%0,%1,%2,%3}, {%4,%5,%6,%7}, {%8,%9}, {%0,%1,%2,%3};"
        : "+f"(c[0]), "+f"(c[1]), "+f"(c[2]), "+f"(c[3])
        : "r"(a[0]), "r"(a[1]), "r"(a[2]), "r"(a[3]), "r"(b0), "r"(b1));
}

// ---------------------------------------------------------------------------
// Weight transpose: wt[n][k] = W[k][n], 1024x1024
// ---------------------------------------------------------------------------
__global__ __launch_bounds__(256) void transpose1024(const float* __restrict__ in,
                                                     float* __restrict__ out) {
    __shared__ float t[32][33];
    int x = blockIdx.x * 32 + threadIdx.x;
    int y = blockIdx.y * 32 + threadIdx.y;
    #pragma unroll
    for (int j = 0; j < 32; j += 8)
        t[threadIdx.y + j][threadIdx.x] = in[(size_t)(y + j) * 1024 + x];
    __syncthreads();
    x = blockIdx.y * 32 + threadIdx.x;
    y = blockIdx.x * 32 + threadIdx.y;
    #pragma unroll
    for (int j = 0; j < 32; j += 8)
        out[(size_t)(y + j) * 1024 + x] = t[threadIdx.x][threadIdx.y + j];
}

// ---------------------------------------------------------------------------
// tf32 mma.sync GEMM for projections: D[m][n] = sum_k A[m][k] * B[n][k]
// Block 128x128, K-chunk 32, 8 warps (2x4), warp tile 64x32.
// EPI: 4 plain fp32 + bias | 5 half head-major + bias | 6 half vT + bias
// ---------------------------------------------------------------------------
template <int EPI>
__global__ __launch_bounds__(256) void mma_gemm(
    const float* __restrict__ Abase, const float* __restrict__ Bbase,
    const float* __restrict__ bias, void* __restrict__ obase)
{
    constexpr int NC = 32;
    extern __shared__ char smem[];
    const int tid = threadIdx.x, lane = tid & 31, warp = tid >> 5;
    const int wm = warp >> 2, wn = warp & 3;
    const int m0 = blockIdx.y * 128, n0 = blockIdx.x * 128;
    const float* A = Abase;
    const float* B = Bbase;

    uint32_t sb = smem_u32(smem);
    const uint32_t AsB[2] = { sb, sb + 16384u };
    const uint32_t BsB[2] = { sb + 32768u, sb + 49152u };

    float c[4][4][4] = {};

    const int lrow = tid >> 3, lseg = tid & 7;
    float4 ar[4], br[4];

    #pragma unroll
    for (int p = 0; p < 4; ++p) {
        ar[p] = *(const float4*)(A + (size_t)(m0 + lrow + p * 32) * 1024 + lseg * 4);
        br[p] = *(const float4*)(B + (size_t)(n0 + lrow + p * 32) * 1024 + lseg * 4);
    }
    #pragma unroll
    for (int p = 0; p < 4; ++p) {
        int r = lrow + p * 32;
        uint32_t da = AsB[0] + (uint32_t)(r * 128) + (uint32_t)((lseg ^ (r & 7)) << 4);
        asm volatile("st.shared.v4.b32 [%0], {%1,%2,%3,%4};" :: "r"(da),
            "r"(f2tf32(ar[p].x)), "r"(f2tf32(ar[p].y)),
            "r"(f2tf32(ar[p].z)), "r"(f2tf32(ar[p].w)) : "memory");
        uint32_t db = BsB[0] + (uint32_t)(r * 128) + (uint32_t)((lseg ^ (r & 7)) << 4);
        asm volatile("st.shared.v4.b32 [%0], {%1,%2,%3,%4};" :: "r"(db),
            "r"(f2tf32(br[p].x)), "r"(f2tf32(br[p].y)),
            "r"(f2tf32(br[p].z)), "r"(f2tf32(br[p].w)) : "memory");
    }

    #pragma unroll 1
    for (int ci = 0; ci < NC; ++ci) {
        __syncthreads();
        if (ci + 1 < NC) {
            #pragma unroll
            for (int p = 0; p < 4; ++p) {
                ar[p] = *(const float4*)(A + (size_t)(m0 + lrow + p * 32) * 1024
                                         + (ci + 1) * 32 + lseg * 4);
                br[p] = *(const float4*)(B + (size_t)(n0 + lrow + p * 32) * 1024
                                         + (ci + 1) * 32 + lseg * 4);
            }
        }
        const int buf = ci & 1;
        #pragma unroll
        for (int ks = 0; ks < 4; ++ks) {
            uint32_t a[4][4];
            #pragma unroll
            for (int mt = 0; mt < 4; ++mt) {
                int row = wm * 64 + mt * 16 + (lane & 15);
                int seg = ks * 2 + (lane >> 4);
                uint32_t addr = AsB[buf] + (uint32_t)(row * 128)
                              + (uint32_t)((seg ^ (row & 7)) << 4);
                asm volatile("ldmatrix.sync.aligned.m8n8.x4.shared.b16 {%0,%1,%2,%3}, [%4];"
                    : "=r"(a[mt][0]), "=r"(a[mt][1]), "=r"(a[mt][2]), "=r"(a[mt][3])
                    : "r"(addr));
            }
            #pragma unroll
            for (int nt = 0; nt < 4; ++nt) {
                int nl = wn * 32 + nt * 8 + (lane >> 2);
                uint32_t b0a = BsB[buf] + (uint32_t)(nl * 128)
                             + (uint32_t)((((ks * 2) ^ (nl & 7)) << 4) + (lane & 3) * 4);
                uint32_t b1a = BsB[buf] + (uint32_t)(nl * 128)
                             + (uint32_t)((((ks * 2 + 1) ^ (nl & 7)) << 4) + (lane & 3) * 4);
                uint32_t b0, b1;
                asm volatile("ld.shared.b32 %0, [%1];" : "=r"(b0) : "r"(b0a));
                asm volatile("ld.shared.b32 %0, [%1];" : "=r"(b1) : "r"(b1a));
                #pragma unroll
                for (int mt = 0; mt < 4; ++mt) {
                    asm volatile(
                        "mma.sync.aligned.m16n8k8.row.col.f32.tf32.tf32.f32 "
                        "{%0,%1,%2,%3}, {%4,%5,%6,%7}, {%8,%9}, {%0,%1,%2,%3};"
                        : "+f"(c[mt][nt][0]), "+f"(c[mt][nt][1]),
                          "+f"(c[mt][nt][2]), "+f"(c[mt][nt][3])
                        : "r"(a[mt][0]), "r"(a[mt][1]), "r"(a[mt][2]), "r"(a[mt][3]),
                          "r"(b0), "r"(b1));
                }
            }
        }
        if (ci + 1 < NC) {
            const int nb = (ci + 1) & 1;
            #pragma unroll
            for (int p = 0; p < 4; ++p) {
                int r = lrow + p * 32;
                uint32_t da = AsB[nb] + (uint32_t)(r * 128) + (uint32_t)((lseg ^ (r & 7)) << 4);
                asm volatile("st.shared.v4.b32 [%0], {%1,%2,%3,%4};" :: "r"(da),
                    "r"(f2tf32(ar[p].x)), "r"(f2tf32(ar[p].y)),
                    "r"(f2tf32(ar[p].z)), "r"(f2tf32(ar[p].w)) : "memory");
                uint32_t db = BsB[nb] + (uint32_t)(r * 128) + (uint32_t)((lseg ^ (r & 7)) << 4);
                asm volatile("st.shared.v4.b32 [%0], {%1,%2,%3,%4};" :: "r"(db),
                    "r"(f2tf32(br[p].x)), "r"(f2tf32(br[p].y)),
                    "r"(f2tf32(br[p].z)), "r"(f2tf32(br[p].w)) : "memory");
            }
        }
    }

    const int mwb = m0 + wm * 64;
    const int nwb = n0 + wn * 32;
    #pragma unroll
    for (int mt = 0; mt < 4; ++mt) {
        #pragma unroll
        for (int nt = 0; nt < 4; ++nt) {
            const int mr = mwb + mt * 16 + (lane >> 2);
            const int nc = nwb + nt * 8 + 2 * (lane & 3);
            float v0 = c[mt][nt][0], v1 = c[mt][nt][1];
            float v2 = c[mt][nt][2], v3 = c[mt][nt][3];
            float2 bb = *(const float2*)(bias + nc);

            if constexpr (EPI == 4) {          // plain fp32 + bias
                float* o = (float*)obase;
                float2 o0 = { v0 + bb.x, v1 + bb.y };
                float2 o1 = { v2 + bb.x, v3 + bb.y };
                *(float2*)(o + (size_t)mr * 1024 + nc) = o0;
                *(float2*)(o + (size_t)(mr + 8) * 1024 + nc) = o1;
            } else if constexpr (EPI == 5) {   // half head-major + bias
                __half* o = (__half*)obase;
                int h = nc >> 6, dd = nc & 63;
                int b = mr >> 11, s = mr & 2047;
                *(uint32_t*)(o + (((size_t)(b * HHc + h) * 2048 + s) * 64 + dd)) =
                    pack_h2(v0 + bb.x, v1 + bb.y);
                *(uint32_t*)(o + (((size_t)(b * HHc + h) * 2048 + (s + 8)) * 64 + dd)) =
                    pack_h2(v2 + bb.x, v3 + bb.y);
            } else {                           // half transposed V: [bh][dd][s]
                __half* o = (__half*)obase;
                int h = nc >> 6, dd = nc & 63;
                int b = mr >> 11, s = mr & 2047;
                size_t base = ((size_t)(b * HHc + h) * 64 + dd) * 2048;
                o[base + s] = __float2half(v0 + bb.x);
                o[base + 2048 + s] = __float2half(v1 + bb.y);
                o[base + s + 8] = __float2half(v2 + bb.x);
                o[base + 2048 + s + 8] = __float2half(v3 + bb.y);
            }
        }
    }
}

// ---------------------------------------------------------------------------
// Fused attention: per block = 16 q-rows of one (b,h).
//   scores (fp16 mma, 128 KB smem strip) -> mask -> softmax -> write attn
//   -> P@V (fp16 mma) -> rep.  K/V staged through 3-deep cp.async ring.
// ---------------------------------------------------------------------------
static constexpr int SROW  = 2052;                       // sS row stride (floats)
static constexpr int RING0 = 16 * SROW * 4;              // 131328 B
static constexpr int SLOT  = 18432;                      // ring slot bytes
static constexpr int RINVO = RING0 + 3 * SLOT;           // 186624
static constexpr int SMEMF = RINVO + 64;                 // 186688 B

__device__ __forceinline__ void stage_k(uint32_t dst, const __half* kp,
                                        int bh, int n0, int tid) {
    #pragma unroll
    for (int p = 0; p < 4; ++p) {
        int id = tid + p * 256;
        int r = id >> 3, seg = id & 7;
        uint32_t d = dst + (uint32_t)(r * 144 + seg * 16);
        const __half* s = kp + ((size_t)bh * 2048 + n0 + r) * 64 + seg * 8;
        asm volatile("cp.async.cg.shared.global [%0], [%1], 16;" :: "r"(d), "l"(s) : "memory");
    }
    asm volatile("cp.async.commit_group;" ::: "memory");
}
__device__ __forceinline__ void stage_v(uint32_t dst, const __half* vp,
                                        int bh, int k0, int tid) {
    #pragma unroll
    for (int p = 0; p < 4; ++p) {
        int id = tid + p * 256;
        int n = id >> 4, seg = id & 15;
        uint32_t d = dst + (uint32_t)(n * 272 + seg * 16);
        const __half* s = vp + ((size_t)bh * 64 + n) * 2048 + k0 + seg * 8;
        asm volatile("cp.async.cg.shared.global [%0], [%1], 16;" :: "r"(d), "l"(s) : "memory");
    }
    asm volatile("cp.async.commit_group;" ::: "memory");
}
__device__ __forceinline__ void wait_tail(int rem) {
    if (rem >= 2)      asm volatile("cp.async.wait_group 2;" ::: "memory");
    else if (rem == 1) asm volatile("cp.async.wait_group 1;" ::: "memory");
    else               asm volatile("cp.async.wait_group 0;" ::: "memory");
}

__global__ __launch_bounds__(256, 1) void fused_attn(
    const __half* __restrict__ qh, const __half* __restrict__ kh,
    const __half* __restrict__ vTh, const float* __restrict__ Mask,
    float* __restrict__ attn, float* __restrict__ rep)
{
    extern __shared__ char smem[];
    const int tid = threadIdx.x, lane = tid & 31, warp = tid >> 5;
    const int bh = blockIdx.y, b = bh >> 4, h = bh & 15;
    const int m0 = blockIdx.x * 16;
    const int r0 = lane >> 2, kq = (lane & 3) * 2;

    float* sS = (float*)smem;                       // [16][SROW]
    float* sRinv = (float*)(smem + RINVO);
    uint32_t ring = smem_u32(smem) + RING0;

    // Q fragments (held in registers for the whole QK phase)
    uint32_t aq[4][4];
    {
        const __half* qb = qh + ((size_t)bh * 2048 + m0) * 64;
        #pragma unroll
        for (int ks = 0; ks < 4; ++ks) {
            aq[ks][0] = *(const uint32_t*)(qb + (size_t)r0 * 64 + ks * 16 + kq);
            aq[ks][1] = *(const uint32_t*)(qb + (size_t)(r0 + 8) * 64 + ks * 16 + kq);
            aq[ks][2] = *(const uint32_t*)(qb + (size_t)r0 * 64 + ks * 16 + 8 + kq);
            aq[ks][3] = *(const uint32_t*)(qb + (size_t)(r0 + 8) * 64 + ks * 16 + 8 + kq);
        }
    }

    // ---- Phase 1: scores ----
    stage_k(ring + 0 * SLOT, kh, bh, 0, tid);
    stage_k(ring + 1 * SLOT, kh, bh, 128, tid);
    stage_k(ring + 2 * SLOT, kh, bh, 256, tid);

    const float* Mb = Mask + (size_t)b * SSc * SSc;
    #pragma unroll 1
    for (int c = 0; c < 16; ++c) {
        wait_tail(15 - c);
        __syncthreads();
        const uint32_t base = ring + (uint32_t)((c % 3) * SLOT);
        const int n0 = c * 128;
        #pragma unroll
        for (int t2 = 0; t2 < 2; ++t2) {
            float acc[4] = {0.f, 0.f, 0.f, 0.f};
            const int nrow = warp * 16 + t2 * 8 + r0;
            const uint32_t baddr = base + (uint32_t)(nrow * 144 + kq * 2);
            #pragma unroll
            for (int ks = 0; ks < 4; ++ks) {
                uint32_t b0, b1;
                asm volatile("ld.shared.b32 %0, [%1];" : "=r"(b0) : "r"(baddr + ks * 32));
                asm volatile("ld.shared.b32 %0, [%1];" : "=r"(b1) : "r"(baddr + ks * 32 + 16));
                mma_f16(acc, aq[ks], b0, b1);
            }
            const int cc = n0 + warp * 16 + t2 * 8 + 2 * (lane & 3);
            const int mr = m0 + r0;
            float2 mk0 = *(const float2*)(Mb + (size_t)mr * SSc + cc);
            float2 mk1 = *(const float2*)(Mb + (size_t)(mr + 8) * SSc + cc);
            *(float2*)(sS + r0 * SROW + cc) =
                make_float2(acc[0] * 0.125f + mk0.x * (-1e9f),
                            acc[1] * 0.125f + mk0.y * (-1e9f));
            *(float2*)(sS + (r0 + 8) * SROW + cc) =
                make_float2(acc[2] * 0.125f + mk1.x * (-1e9f),
                            acc[3] * 0.125f + mk1.y * (-1e9f));
        }
        __syncthreads();
        if (c + 3 < 16) stage_k(ring + (uint32_t)(((c + 3) % 3) * SLOT), kh, bh, (c + 3) * 128, tid);
    }

    // prefetch first PV chunks (overlaps with softmax)
    stage_v(ring + 0 * SLOT, vTh, bh, 0, tid);
    stage_v(ring + 1 * SLOT, vTh, bh, 128, tid);
    stage_v(ring + 2 * SLOT, vTh, bh, 256, tid);

    // ---- Phase 2: softmax (strip fully in smem) ----
    {
        const int row = tid >> 4, half = tid & 15;
        float* rp = sS + row * SROW;
        float mx = -3.4e38f;
        #pragma unroll 4
        for (int j = 0; j < 128; ++j) mx = fmaxf(mx, rp[half + j * 16]);
        #pragma unroll
        for (int o = 8; o; o >>= 1) mx = fmaxf(mx, __shfl_xor_sync(0xffffffffu, mx, o));
        float sum = 0.f;
        #pragma unroll 4
        for (int j = 0; j < 128; ++j) {
            float e = __expf(rp[half + j * 16] - mx);
            rp[half + j * 16] = e;
            sum += e;
        }
        #pragma unroll
        for (int o = 8; o; o >>= 1) sum += __shfl_xor_sync(0xffffffffu, sum, o);
        if (half == 0) sRinv[row] = 1.0f / sum;
    }
    __syncthreads();

    // write normalized attn (coalesced float4)
    {
        float* ab = attn + (size_t)bh * SSc * SSc + (size_t)m0 * SSc;
        #pragma unroll 4
        for (int j = 0; j < 32; ++j) {
            int f = tid + j * 256;
            int r = f >> 9, c4 = f & 511;
            float4 e = *(const float4*)(sS + r * SROW + c4 * 4);
            float rv = sRinv[r];
            float4 o = { e.x * rv, e.y * rv, e.z * rv, e.w * rv };
            *(float4*)(ab + (size_t)r * SSc + c4 * 4) = o;
        }
    }

    // ---- Phase 3: P @ V ----
    float pv[4] = {0.f, 0.f, 0.f, 0.f};
    #pragma unroll 1
    for (int c = 0; c < 16; ++c) {
        wait_tail(15 - c);
        __syncthreads();
        const uint32_t base = ring + (uint32_t)((c % 3) * SLOT);
        const int k0 = c * 128;
        const uint32_t brow = base + (uint32_t)((warp * 8 + r0) * 272 + kq * 2);
        #pragma unroll
        for (int ks = 0; ks < 8; ++ks) {
            const int kk = k0 + ks * 16 + kq;
            float2 a0 = *(const float2*)(sS + r0 * SROW + kk);
            float2 a1 = *(const float2*)(sS + (r0 + 8) * SROW + kk);
            float2 a2 = *(const float2*)(sS + r0 * SROW + kk + 8);
            float2 a3 = *(const float2*)(sS + (r0 + 8) * SROW + kk + 8);
            uint32_t A[4] = { pack_h2(a0.x, a0.y), pack_h2(a1.x, a1.y),
                              pack_h2(a2.x, a2.y), pack_h2(a3.x, a3.y) };
            uint32_t b0, b1;
            asm volatile("ld.shared.b32 %0, [%1];" : "=r"(b0) : "r"(brow + ks * 32));
            asm volatile("ld.shared.b32 %0, [%1];" : "=r"(b1) : "r"(brow + ks * 32 + 16));
            mma_f16(pv, A, b0, b1);
        }
        __syncthreads();
        if (c + 3 < 16) stage_v(ring + (uint32_t)(((c + 3) % 3) * SLOT), vTh, bh, (c + 3) * 128, tid);
    }

    // epilogue: rep (concat layout), fold in 1/sum
    {
        const float ri0 = sRinv[r0], ri1 = sRinv[r0 + 8];
        const int dd = warp * 8 + 2 * (lane & 3);
        float2 o0 = { pv[0] * ri0, pv[1] * ri0 };
        float2 o1 = { pv[2] * ri1, pv[3] * ri1 };
        *(float2*)(rep + ((size_t)(b * 2048 + m0 + r0)) * 1024 + h * 64 + dd) = o0;
        *(float2*)(rep + ((size_t)(b * 2048 + m0 + r0 + 8)) * 1024 + h * 64 + dd) = o1;
    }
}

// ---------------------------------------------------------------------------
// Launch
// ---------------------------------------------------------------------------
static constexpr size_t SMEMP = 65536;  // projection GEMM smem

extern "C" void kernel_launch(void* const* d_in, const int* in_sizes, int n_in,
                              void* d_out, int out_size)
{
    const float* Q    = (const float*)d_in[0];
    const float* K    = (const float*)d_in[1];
    const float* V    = (const float*)d_in[2];
    const float* Mask = (const float*)d_in[3];
    const float* Wq   = (const float*)d_in[4];
    const float* bq   = (const float*)d_in[5];
    const float* Wk   = (const float*)d_in[6];
    const float* bk   = (const float*)d_in[7];
    const float* Wv   = (const float*)d_in[8];
    const float* bv   = (const float*)d_in[9];
    const float* Wo   = (const float*)d_in[10];
    const float* bo   = (const float*)d_in[11];
    float* out = (float*)d_out;

    __half *qh, *kh, *vTh;
    float *rep, *wt;
    {
        void* p;
        cudaGetSymbolAddress(&p, g_qh);  qh  = (__half*)p;
        cudaGetSymbolAddress(&p, g_kh);  kh  = (__half*)p;
        cudaGetSymbolAddress(&p, g_vTh); vTh = (__half*)p;
        cudaGetSymbolAddress(&p, g_rep); rep = (float*)p;
        cudaGetSymbolAddress(&p, g_wt);  wt  = (float*)p;
    }
    float* wqT = wt;
    float* wkT = wt + (size_t)1024 * 1024;
    float* wvT = wt + (size_t)2 * 1024 * 1024;
    float* woT = wt + (size_t)3 * 1024 * 1024;

    float* attn;
    if ((size_t)out_size >= OUT_ELEMS + ATTN_ELEMS) {
        attn = out + OUT_ELEMS;
    } else {
        void* p;
        cudaGetSymbolAddress(&p, g_attn_fb);
        attn = (float*)p;
    }

    cudaFuncSetAttribute(mma_gemm<4>, cudaFuncAttributeMaxDynamicSharedMemorySize, SMEMP);
    cudaFuncSetAttribute(mma_gemm<5>, cudaFuncAttributeMaxDynamicSharedMemorySize, SMEMP);
    cudaFuncSetAttribute(mma_gemm<6>, cudaFuncAttributeMaxDynamicSharedMemorySize, SMEMP);
    cudaFuncSetAttribute(fused_attn, cudaFuncAttributeMaxDynamicSharedMemorySize, SMEMF);

    dim3 tb(32, 8), tg(32, 32);
    transpose1024<<<tg, tb>>>(Wq, wqT);
    transpose1024<<<tg, tb>>>(Wk, wkT);
    transpose1024<<<tg, tb>>>(Wv, wvT);
    transpose1024<<<tg, tb>>>(Wo, woT);

    // Projections (M=8192, N=1024, K=1024), outputs fp16
    dim3 gp(8, 64);
    mma_gemm<5><<<gp, 256, SMEMP>>>(Q, wqT, bq, qh);
    mma_gemm<5><<<gp, 256, SMEMP>>>(K, wkT, bk, kh);
    mma_gemm<6><<<gp, 256, SMEMP>>>(V, wvT, bv, vTh);

    // Fused scores + softmax + attn-write + P@V
    dim3 gf(128, 64);
    fused_attn<<<gf, 256, SMEMF>>>(qh, kh, vTh, Mask, attn, rep);

    // out = rep @ Wo + bo (fp32)
    mma_gemm<4><<<gp, 256, SMEMP>>>(rep, woT, bo, out);
}

// round 6
// speedup vs baseline: 1.4734x; 1.4734x over previous
#include <cuda_runtime.h>
#include <cuda_fp16.h>
#include <cstdint>

// B=4, S=2048, D=1024, H=16, depth=64
static constexpr int BBc = 4;
static constexpr int SSc = 2048;
static constexpr int HHc = 16;
static constexpr size_t OUT_ELEMS  = (size_t)8388608;    // B*S*D
static constexpr size_t ATTN_ELEMS = (size_t)268435456;  // B*H*S*S

// Static scratch
__device__ __half g_qh[OUT_ELEMS];        // [B*H][2048][64] fp16
__device__ __half g_kh[OUT_ELEMS];        // [B*H][2048][64] fp16
__device__ float  g_vT[OUT_ELEMS];        // [B*H][64][2048] fp32
__device__ float  g_rep[OUT_ELEMS];       // [B,S,D] concat fp32
__device__ float  g_wt[4][1024 * 1024];   // transposed weights [n][k]
__device__ float  g_attn_fb[ATTN_ELEMS];  // fallback

__device__ __forceinline__ uint32_t smem_u32(const void* p) {
    uint32_t a;
    asm("{ .reg .u64 t; cvta.to.shared.u64 t, %1; cvt.u32.u64 %0, t; }" : "=r"(a) : "l"(p));
    return a;
}
__device__ __forceinline__ uint32_t f2tf32(float f) {
    uint32_t r;
    asm("cvt.rna.tf32.f32 %0, %1;" : "=r"(r) : "f"(f));
    return r;
}
__device__ __forceinline__ uint32_t pack_h2(float lo, float hi) {
    uint32_t r;
    asm("cvt.rn.f16x2.f32 %0, %1, %2;" : "=r"(r) : "f"(hi), "f"(lo));
    return r;
}

// ---------------------------------------------------------------------------
// Weight transpose: wt[n][k] = W[k][n], 1024x1024
// ---------------------------------------------------------------------------
__global__ __launch_bounds__(256) void transpose1024(const float* __restrict__ in,
                                                     float* __restrict__ out) {
    __shared__ float t[32][33];
    int x = blockIdx.x * 32 + threadIdx.x;
    int y = blockIdx.y * 32 + threadIdx.y;
    #pragma unroll
    for (int j = 0; j < 32; j += 8)
        t[threadIdx.y + j][threadIdx.x] = in[(size_t)(y + j) * 1024 + x];
    __syncthreads();
    x = blockIdx.y * 32 + threadIdx.x;
    y = blockIdx.x * 32 + threadIdx.y;
    #pragma unroll
    for (int j = 0; j < 32; j += 8)
        out[(size_t)(y + j) * 1024 + x] = t[threadIdx.x][threadIdx.y + j];
}

// ---------------------------------------------------------------------------
// tf32 mma.sync GEMM: D[m][n] = sum_k A[m][k] * B[n][k] (fp32 in)
// Block tile 128 x NT, K-chunk 32, 8 warps.
// EPI: 1 fp32 vT+bias | 3 rep->concat | 4 plain fp32+bias | 5 fp16 head-major+bias
// ---------------------------------------------------------------------------
template <int NT, int NC, int EPI>
__global__ __launch_bounds__(256) void mma_gemm(
    const float* __restrict__ Abase, int lda, long aBS,
    const float* __restrict__ Bbase, int ldb, long bBS,
    const float* __restrict__ bias, void* __restrict__ obase)
{
    constexpr int WM  = (NT == 128) ? 2 : 4;
    constexpr int WN  = 8 / WM;
    constexpr int WTM = 128 / WM;
    constexpr int WTN = NT / WN;
    constexpr int MT  = WTM / 16;
    constexpr int NTt = WTN / 8;
    constexpr int BP  = NT / 32;

    extern __shared__ char smem[];
    const int tid = threadIdx.x, lane = tid & 31, warp = tid >> 5;
    const int wm = warp / WN, wn = warp % WN;
    const int z = blockIdx.z;
    const int m0 = blockIdx.y * 128, n0 = blockIdx.x * NT;
    const float* A = Abase + (size_t)z * aBS;
    const float* B = Bbase + (size_t)z * bBS;

    uint32_t sb = smem_u32(smem);
    const uint32_t AsB[2] = { sb, sb + 16384u };
    const uint32_t BsB[2] = { sb + 32768u, sb + 32768u + (uint32_t)NT * 128u };

    float c[MT][NTt][4] = {};

    const int lrow = tid >> 3, lseg = tid & 7;
    float4 ar[4], br[BP];

    #pragma unroll
    for (int p = 0; p < 4; ++p)
        ar[p] = *(const float4*)(A + (size_t)(m0 + lrow + p * 32) * lda + lseg * 4);
    #pragma unroll
    for (int p = 0; p < BP; ++p)
        br[p] = *(const float4*)(B + (size_t)(n0 + lrow + p * 32) * ldb + lseg * 4);
    #pragma unroll
    for (int p = 0; p < 4; ++p) {
        int r = lrow + p * 32;
        uint32_t d = AsB[0] + (uint32_t)(r * 128) + (uint32_t)((lseg ^ (r & 7)) << 4);
        asm volatile("st.shared.v4.b32 [%0], {%1,%2,%3,%4};" :: "r"(d),
            "r"(f2tf32(ar[p].x)), "r"(f2tf32(ar[p].y)),
            "r"(f2tf32(ar[p].z)), "r"(f2tf32(ar[p].w)) : "memory");
    }
    #pragma unroll
    for (int p = 0; p < BP; ++p) {
        int r = lrow + p * 32;
        uint32_t d = BsB[0] + (uint32_t)(r * 128) + (uint32_t)((lseg ^ (r & 7)) << 4);
        asm volatile("st.shared.v4.b32 [%0], {%1,%2,%3,%4};" :: "r"(d),
            "r"(f2tf32(br[p].x)), "r"(f2tf32(br[p].y)),
            "r"(f2tf32(br[p].z)), "r"(f2tf32(br[p].w)) : "memory");
    }

    #pragma unroll 1
    for (int ci = 0; ci < NC; ++ci) {
        __syncthreads();
        if (ci + 1 < NC) {
            #pragma unroll
            for (int p = 0; p < 4; ++p)
                ar[p] = *(const float4*)(A + (size_t)(m0 + lrow + p * 32) * lda
                                         + (ci + 1) * 32 + lseg * 4);
            #pragma unroll
            for (int p = 0; p < BP; ++p)
                br[p] = *(const float4*)(B + (size_t)(n0 + lrow + p * 32) * ldb
                                         + (ci + 1) * 32 + lseg * 4);
        }
        const int buf = ci & 1;
        #pragma unroll
        for (int ks = 0; ks < 4; ++ks) {
            uint32_t a[MT][4];
            #pragma unroll
            for (int mt = 0; mt < MT; ++mt) {
                int row = wm * WTM + mt * 16 + (lane & 15);
                int seg = ks * 2 + (lane >> 4);
                uint32_t addr = AsB[buf] + (uint32_t)(row * 128)
                              + (uint32_t)((seg ^ (row & 7)) << 4);
                asm volatile("ldmatrix.sync.aligned.m8n8.x4.shared.b16 {%0,%1,%2,%3}, [%4];"
                    : "=r"(a[mt][0]), "=r"(a[mt][1]), "=r"(a[mt][2]), "=r"(a[mt][3])
                    : "r"(addr));
            }
            #pragma unroll
            for (int nt = 0; nt < NTt; ++nt) {
                int nl = wn * WTN + nt * 8 + (lane >> 2);
                uint32_t b0a = BsB[buf] + (uint32_t)(nl * 128)
                             + (uint32_t)((((ks * 2) ^ (nl & 7)) << 4) + (lane & 3) * 4);
                uint32_t b1a = BsB[buf] + (uint32_t)(nl * 128)
                             + (uint32_t)((((ks * 2 + 1) ^ (nl & 7)) << 4) + (lane & 3) * 4);
                uint32_t b0, b1;
                asm volatile("ld.shared.b32 %0, [%1];" : "=r"(b0) : "r"(b0a));
                asm volatile("ld.shared.b32 %0, [%1];" : "=r"(b1) : "r"(b1a));
                #pragma unroll
                for (int mt = 0; mt < MT; ++mt) {
                    asm volatile(
                        "mma.sync.aligned.m16n8k8.row.col.f32.tf32.tf32.f32 "
                        "{%0,%1,%2,%3}, {%4,%5,%6,%7}, {%8,%9}, {%0,%1,%2,%3};"
                        : "+f"(c[mt][nt][0]), "+f"(c[mt][nt][1]),
                          "+f"(c[mt][nt][2]), "+f"(c[mt][nt][3])
                        : "r"(a[mt][0]), "r"(a[mt][1]), "r"(a[mt][2]), "r"(a[mt][3]),
                          "r"(b0), "r"(b1));
                }
            }
        }
        if (ci + 1 < NC) {
            const int nb = (ci + 1) & 1;
            #pragma unroll
            for (int p = 0; p < 4; ++p) {
                int r = lrow + p * 32;
                uint32_t d = AsB[nb] + (uint32_t)(r * 128) + (uint32_t)((lseg ^ (r & 7)) << 4);
                asm volatile("st.shared.v4.b32 [%0], {%1,%2,%3,%4};" :: "r"(d),
                    "r"(f2tf32(ar[p].x)), "r"(f2tf32(ar[p].y)),
                    "r"(f2tf32(ar[p].z)), "r"(f2tf32(ar[p].w)) : "memory");
            }
            #pragma unroll
            for (int p = 0; p < BP; ++p) {
                int r = lrow + p * 32;
                uint32_t d = BsB[nb] + (uint32_t)(r * 128) + (uint32_t)((lseg ^ (r & 7)) << 4);
                asm volatile("st.shared.v4.b32 [%0], {%1,%2,%3,%4};" :: "r"(d),
                    "r"(f2tf32(br[p].x)), "r"(f2tf32(br[p].y)),
                    "r"(f2tf32(br[p].z)), "r"(f2tf32(br[p].w)) : "memory");
            }
        }
    }

    const int mwb = m0 + wm * WTM;
    const int nwb = n0 + wn * WTN;
    #pragma unroll
    for (int mt = 0; mt < MT; ++mt) {
        #pragma unroll
        for (int nt = 0; nt < NTt; ++nt) {
            const int mr = mwb + mt * 16 + (lane >> 2);
            const int nc = nwb + nt * 8 + 2 * (lane & 3);
            float v0 = c[mt][nt][0], v1 = c[mt][nt][1];
            float v2 = c[mt][nt][2], v3 = c[mt][nt][3];

            if constexpr (EPI == 1) {          // fp32 transposed V: [bh][dd][s]
                float* o = (float*)obase;
                float2 bb = *(const float2*)(bias + nc);
                int h = nc >> 6, dd = nc & 63;
                int b = mr >> 11, s = mr & 2047;
                size_t base = ((size_t)(b * HHc + h) * 64 + dd) * 2048;
                o[base + s] = v0 + bb.x;
                o[base + 2048 + s] = v1 + bb.y;
                o[base + s + 8] = v2 + bb.x;
                o[base + 2048 + s + 8] = v3 + bb.y;
            } else if constexpr (EPI == 3) {   // rep -> concat [B,S,D]
                float* o = (float*)obase;
                int b = z >> 4, h = z & 15;
                float2 o0 = { v0, v1 };
                float2 o1 = { v2, v3 };
                *(float2*)(o + ((size_t)(b * 2048 + mr)) * 1024 + h * 64 + nc) = o0;
                *(float2*)(o + ((size_t)(b * 2048 + mr + 8)) * 1024 + h * 64 + nc) = o1;
            } else if constexpr (EPI == 4) {   // plain fp32 + bias
                float* o = (float*)obase;
                float2 bb = *(const float2*)(bias + nc);
                float2 o0 = { v0 + bb.x, v1 + bb.y };
                float2 o1 = { v2 + bb.x, v3 + bb.y };
                *(float2*)(o + (size_t)mr * 1024 + nc) = o0;
                *(float2*)(o + (size_t)(mr + 8) * 1024 + nc) = o1;
            } else {                           // EPI 5: fp16 head-major + bias
                __half* o = (__half*)obase;
                float2 bb = *(const float2*)(bias + nc);
                int h = nc >> 6, dd = nc & 63;
                int b = mr >> 11, s = mr & 2047;
                *(uint32_t*)(o + (((size_t)(b * HHc + h) * 2048 + s) * 64 + dd)) =
                    pack_h2(v0 + bb.x, v1 + bb.y);
                *(uint32_t*)(o + (((size_t)(b * HHc + h) * 2048 + (s + 8)) * 64 + dd)) =
                    pack_h2(v2 + bb.x, v3 + bb.y);
            }
        }
    }
}

// ---------------------------------------------------------------------------
// fp16 scores kernel: per (b,h) 128x128 tile of scores = q@k^T*0.125 + mask*-1e9
// K = 64 in one shot. smem 32 KB. 8 warps (2x4), warp tile 64x32, m16n8k16.
// ---------------------------------------------------------------------------
__global__ __launch_bounds__(256) void scores_f16(
    const __half* __restrict__ qh, const __half* __restrict__ kh,
    const float* __restrict__ Mask, float* __restrict__ attn)
{
    __shared__ __align__(16) uint8_t smem[32768];
    const int tid = threadIdx.x, lane = tid & 31, warp = tid >> 5;
    const int wm = warp >> 2, wn = warp & 3;
    const int bh = blockIdx.z;
    const int m0 = blockIdx.y * 128, n0 = blockIdx.x * 128;

    uint32_t sQ = smem_u32(smem);
    uint32_t sK = sQ + 16384u;

    // Stage q tile (128x64 fp16) and k tile (128x64 fp16) via cp.async
    {
        const __half* qsrc = qh + ((size_t)bh * 2048 + m0) * 64;
        const __half* ksrc = kh + ((size_t)bh * 2048 + n0) * 64;
        #pragma unroll
        for (int p = 0; p < 4; ++p) {
            int id = tid + p * 256;
            int r = id >> 3, seg = id & 7;
            uint32_t off = (uint32_t)(r * 128) + (uint32_t)((seg ^ (r & 7)) << 4);
            asm volatile("cp.async.cg.shared.global [%0], [%1], 16;"
                         :: "r"(sQ + off), "l"(qsrc + (size_t)r * 64 + seg * 8) : "memory");
            asm volatile("cp.async.cg.shared.global [%0], [%1], 16;"
                         :: "r"(sK + off), "l"(ksrc + (size_t)r * 64 + seg * 8) : "memory");
        }
        asm volatile("cp.async.commit_group;" ::: "memory");
        asm volatile("cp.async.wait_group 0;" ::: "memory");
    }
    __syncthreads();

    float c[4][4][4] = {};
    #pragma unroll
    for (int ks = 0; ks < 4; ++ks) {
        uint32_t a[4][4];
        #pragma unroll
        for (int mt = 0; mt < 4; ++mt) {
            int row = wm * 64 + mt * 16 + (lane & 15);
            int seg = ks * 2 + (lane >> 4);
            uint32_t addr = sQ + (uint32_t)(row * 128) + (uint32_t)((seg ^ (row & 7)) << 4);
            asm volatile("ldmatrix.sync.aligned.m8n8.x4.shared.b16 {%0,%1,%2,%3}, [%4];"
                : "=r"(a[mt][0]), "=r"(a[mt][1]), "=r"(a[mt][2]), "=r"(a[mt][3])
                : "r"(addr));
        }
        #pragma unroll
        for (int nt = 0; nt < 4; ++nt) {
            int nl = wn * 32 + nt * 8 + (lane >> 2);
            uint32_t b0a = sK + (uint32_t)(nl * 128)
                         + (uint32_t)((((ks * 2) ^ (nl & 7)) << 4) + (lane & 3) * 4);
            uint32_t b1a = sK + (uint32_t)(nl * 128)
                         + (uint32_t)((((ks * 2 + 1) ^ (nl & 7)) << 4) + (lane & 3) * 4);
            uint32_t b0, b1;
            asm volatile("ld.shared.b32 %0, [%1];" : "=r"(b0) : "r"(b0a));
            asm volatile("ld.shared.b32 %0, [%1];" : "=r"(b1) : "r"(b1a));
            #pragma unroll
            for (int mt = 0; mt < 4; ++mt) {
                asm volatile(
                    "mma.sync.aligned.m16n8k16.row.col.f32.f16.f16.f32 "
                    "{%0,%1,%2,%3}, {%4,%5,%6,%7}, {%8,%9}, {%0,%1,%2,%3};"
                    : "+f"(c[mt][nt][0]), "+f"(c[mt][nt][1]),
                      "+f"(c[mt][nt][2]), "+f"(c[mt][nt][3])
                    : "r"(a[mt][0]), "r"(a[mt][1]), "r"(a[mt][2]), "r"(a[mt][3]),
                      "r"(b0), "r"(b1));
            }
        }
    }

    const float* Mb = Mask + (size_t)(bh >> 4) * SSc * SSc;
    float* Ob = attn + (size_t)bh * SSc * SSc;
    #pragma unroll
    for (int mt = 0; mt < 4; ++mt) {
        #pragma unroll
        for (int nt = 0; nt < 4; ++nt) {
            const int mr = m0 + wm * 64 + mt * 16 + (lane >> 2);
            const int nc = n0 + wn * 32 + nt * 8 + 2 * (lane & 3);
            float2 mk0 = *(const float2*)(Mb + (size_t)mr * SSc + nc);
            float2 mk1 = *(const float2*)(Mb + (size_t)(mr + 8) * SSc + nc);
            float2 o0 = { c[mt][nt][0] * 0.125f + mk0.x * (-1e9f),
                          c[mt][nt][1] * 0.125f + mk0.y * (-1e9f) };
            float2 o1 = { c[mt][nt][2] * 0.125f + mk1.x * (-1e9f),
                          c[mt][nt][3] * 0.125f + mk1.y * (-1e9f) };
            *(float2*)(Ob + (size_t)mr * SSc + nc) = o0;
            *(float2*)(Ob + (size_t)(mr + 8) * SSc + nc) = o1;
        }
    }
}

// ---------------------------------------------------------------------------
// Softmax over rows of length 2048, in place.
// ---------------------------------------------------------------------------
__global__ __launch_bounds__(256) void softmax_rows(float* __restrict__ Attn) {
    const size_t rrow = blockIdx.x;
    float* row = Attn + rrow * 2048;
    const int tid = threadIdx.x;
    __shared__ float red[8];

    float v[8];
    float mx = -3.4e38f;
    #pragma unroll
    for (int i = 0; i < 8; i++) { v[i] = row[tid + i * 256]; mx = fmaxf(mx, v[i]); }
    #pragma unroll
    for (int o = 16; o; o >>= 1) mx = fmaxf(mx, __shfl_xor_sync(0xffffffffu, mx, o));
    if ((tid & 31) == 0) red[tid >> 5] = mx;
    __syncthreads();
    mx = red[0];
    #pragma unroll
    for (int w = 1; w < 8; w++) mx = fmaxf(mx, red[w]);
    __syncthreads();

    float sum = 0.f;
    #pragma unroll
    for (int i = 0; i < 8; i++) { v[i] = __expf(v[i] - mx); sum += v[i]; }
    #pragma unroll
    for (int o = 16; o; o >>= 1) sum += __shfl_xor_sync(0xffffffffu, sum, o);
    if ((tid & 31) == 0) red[tid >> 5] = sum;
    __syncthreads();
    float tot = 0.f;
    #pragma unroll
    for (int w = 0; w < 8; w++) tot += red[w];
    const float rinv = 1.0f / tot;
    #pragma unroll
    for (int i = 0; i < 8; i++) row[tid + i * 256] = v[i] * rinv;
}

// ---------------------------------------------------------------------------
// Launch
// ---------------------------------------------------------------------------
static constexpr size_t SMEM128 = 65536;
static constexpr size_t SMEM64  = 49152;

extern "C" void kernel_launch(void* const* d_in, const int* in_sizes, int n_in,
                              void* d_out, int out_size)
{
    const float* Q    = (const float*)d_in[0];
    const float* K    = (const float*)d_in[1];
    const float* V    = (const float*)d_in[2];
    const float* Mask = (const float*)d_in[3];
    const float* Wq   = (const float*)d_in[4];
    const float* bq   = (const float*)d_in[5];
    const float* Wk   = (const float*)d_in[6];
    const float* bk   = (const float*)d_in[7];
    const float* Wv   = (const float*)d_in[8];
    const float* bv   = (const float*)d_in[9];
    const float* Wo   = (const float*)d_in[10];
    const float* bo   = (const float*)d_in[11];
    float* out = (float*)d_out;

    __half *qh, *kh;
    float *vT, *rep, *wt;
    {
        void* p;
        cudaGetSymbolAddress(&p, g_qh);  qh  = (__half*)p;
        cudaGetSymbolAddress(&p, g_kh);  kh  = (__half*)p;
        cudaGetSymbolAddress(&p, g_vT);  vT  = (float*)p;
        cudaGetSymbolAddress(&p, g_rep); rep = (float*)p;
        cudaGetSymbolAddress(&p, g_wt);  wt  = (float*)p;
    }
    float* wqT = wt;
    float* wkT = wt + (size_t)1024 * 1024;
    float* wvT = wt + (size_t)2 * 1024 * 1024;
    float* woT = wt + (size_t)3 * 1024 * 1024;

    float* attn;
    if ((size_t)out_size >= OUT_ELEMS + ATTN_ELEMS) {
        attn = out + OUT_ELEMS;
    } else {
        void* p;
        cudaGetSymbolAddress(&p, g_attn_fb);
        attn = (float*)p;
    }

    cudaFuncSetAttribute(mma_gemm<128, 32, 5>, cudaFuncAttributeMaxDynamicSharedMemorySize, SMEM128);
    cudaFuncSetAttribute(mma_gemm<128, 32, 1>, cudaFuncAttributeMaxDynamicSharedMemorySize, SMEM128);
    cudaFuncSetAttribute(mma_gemm<64, 64, 3>,  cudaFuncAttributeMaxDynamicSharedMemorySize, SMEM64);
    cudaFuncSetAttribute(mma_gemm<128, 32, 4>, cudaFuncAttributeMaxDynamicSharedMemorySize, SMEM128);

    // Transpose weights -> [n][k]
    dim3 tb(32, 8), tg(32, 32);
    transpose1024<<<tg, tb>>>(Wq, wqT);
    transpose1024<<<tg, tb>>>(Wk, wkT);
    transpose1024<<<tg, tb>>>(Wv, wvT);
    transpose1024<<<tg, tb>>>(Wo, woT);

    // Projections (M=8192, N=1024, K=1024)
    dim3 gp(8, 64, 1);
    mma_gemm<128, 32, 5><<<gp, 256, SMEM128>>>(Q, 1024, 0, wqT, 1024, 0, bq, qh);
    mma_gemm<128, 32, 5><<<gp, 256, SMEM128>>>(K, 1024, 0, wkT, 1024, 0, bk, kh);
    mma_gemm<128, 32, 1><<<gp, 256, SMEM128>>>(V, 1024, 0, wvT, 1024, 0, bv, vT);

    // Scores (per bh: 2048x2048, K=64) + mask, fp16 mma
    dim3 gs(16, 16, BBc * HHc);
    scores_f16<<<gs, 256>>>(qh, kh, Mask, attn);

    softmax_rows<<<BBc * HHc * SSc, 256>>>(attn);

    // rep = attn @ v  (per bh: M=2048, N=64, K=2048), B = vT (fp32)
    dim3 gr(1, 16, BBc * HHc);
    mma_gemm<64, 64, 3><<<gr, 256, SMEM64>>>(attn, 2048, (long)SSc * SSc,
                                             vT, 2048, (long)64 * 2048,
                                             nullptr, rep);

    // out = rep @ Wo + bo (fp32)
    mma_gemm<128, 32, 4><<<gp, 256, SMEM128>>>(rep, 1024, 0, woT, 1024, 0, bo, out);
}